// round 9
// baseline (speedup 1.0000x reference)
#include <cuda_runtime.h>
#include <cuda_fp16.h>
#include <cstdint>

#define TOKENS 32768
#define HID 768
#define INTR 3072
#define NTAGS 64

// ---------------------------------------------------------------------------
// Scratch (static device memory — allocation-free per harness rules)
// ---------------------------------------------------------------------------
__device__ __align__(256) __half g_x[(size_t)TOKENS * HID];    // LN1 out (fp16)
__device__ __align__(256) __half g_h[(size_t)TOKENS * INTR];   // relu(x@W1+b1) fp16
__device__ __align__(256) float  g_ffx[(size_t)TOKENS * HID];  // ff + x (fp32)
__device__ __align__(256) __half g_w1t[(size_t)INTR * HID];    // W1^T [n][k] fp16
__device__ __align__(256) __half g_w2t[(size_t)HID * INTR];    // W2^T [n][k] fp16
__device__ __align__(256) float  g_tmp[NTAGS * HID];           // tag_emb@Wv+bv
__device__ __align__(256) float  g_ptag[NTAGS * HID];          // per-tag vector

// ---------------------------------------------------------------------------
// Helpers
// ---------------------------------------------------------------------------
__device__ __forceinline__ void cp_async16(uint32_t saddr, const void* gaddr) {
    asm volatile("cp.async.cg.shared.global [%0], [%1], 16;" :: "r"(saddr), "l"(gaddr));
}
__device__ __forceinline__ void cp_commit() { asm volatile("cp.async.commit_group;"); }
template<int N> __device__ __forceinline__ void cp_wait() {
    asm volatile("cp.async.wait_group %0;" :: "n"(N));
}

__device__ __forceinline__ void mma_f16(float c[4], const uint32_t a[4],
                                        uint32_t b0, uint32_t b1) {
    asm volatile(
        "mma.sync.aligned.m16n8k16.row.col.f32.f16.f16.f32 "
        "{%0,%1,%2,%3}, {%4,%5,%6,%7}, {%8,%9}, {%0,%1,%2,%3};"
        : "+f"(c[0]), "+f"(c[1]), "+f"(c[2]), "+f"(c[3])
        : "r"(a[0]), "r"(a[1]), "r"(a[2]), "r"(a[3]), "r"(b0), "r"(b1));
}

__device__ __forceinline__ void ldsm_x4(uint32_t r[4], uint32_t addr) {
    asm volatile("ldmatrix.sync.aligned.m8n8.x4.shared.b16 {%0,%1,%2,%3}, [%4];"
        : "=r"(r[0]), "=r"(r[1]), "=r"(r[2]), "=r"(r[3]) : "r"(addr));
}

// ---------------------------------------------------------------------------
// Fused prep kernel: weight transpose+round -> half [n][k], plus tag GEMV tail
// ---------------------------------------------------------------------------
template<int WHICH, int K, int N>
__global__ void __launch_bounds__(256)
prep_kernel(const float* __restrict__ W,
            const float* __restrict__ E,
            const float* __restrict__ Wt,
            const float* __restrict__ bt) {
    __shared__ float sbuf[32 * 33];
    constexpr int TB = (N / 32) * (K / 32);
    const int tid = threadIdx.x;
    const int bid = blockIdx.x;

    if (bid < TB) {
        int nb = bid % (N / 32), kb = bid / (N / 32);
        int tx = tid & 31, ty = tid >> 5;
        float (*tile)[33] = (float(*)[33])sbuf;
#pragma unroll
        for (int i = ty; i < 32; i += 8)
            tile[i][tx] = W[(long)(kb * 32 + i) * N + nb * 32 + tx];
        __syncthreads();
        __half* out = WHICH ? g_w2t : g_w1t;
#pragma unroll
        for (int i = ty; i < 32; i += 8)
            out[(long)(nb * 32 + i) * K + kb * 32 + tx] = __float2half_rn(tile[tx][i]);
    } else {
        int b2 = bid - TB;
        int t = b2 / 3, chunk = b2 - t * 3;
        int n = chunk * 256 + tid;
        const float* Es = WHICH ? g_tmp : E;
        float* O = WHICH ? g_ptag : g_tmp;
        for (int c = tid; c < HID; c += 256) sbuf[c] = Es[t * HID + c];
        __syncthreads();
        float a0 = bt[n], a1 = 0.f, a2 = 0.f, a3 = 0.f;
        for (int k = 0; k < HID; k += 8) {
            float w0 = Wt[(long)(k + 0) * HID + n];
            float w1 = Wt[(long)(k + 1) * HID + n];
            float w2 = Wt[(long)(k + 2) * HID + n];
            float w3 = Wt[(long)(k + 3) * HID + n];
            float w4 = Wt[(long)(k + 4) * HID + n];
            float w5 = Wt[(long)(k + 5) * HID + n];
            float w6 = Wt[(long)(k + 6) * HID + n];
            float w7 = Wt[(long)(k + 7) * HID + n];
            a0 = fmaf(sbuf[k + 0], w0, a0);
            a1 = fmaf(sbuf[k + 1], w1, a1);
            a2 = fmaf(sbuf[k + 2], w2, a2);
            a3 = fmaf(sbuf[k + 3], w3, a3);
            a0 = fmaf(sbuf[k + 4], w4, a0);
            a1 = fmaf(sbuf[k + 5], w5, a1);
            a2 = fmaf(sbuf[k + 6], w6, a2);
            a3 = fmaf(sbuf[k + 7], w7, a3);
        }
        O[t * HID + n] = (a0 + a1) + (a2 + a3);
    }
}

// ---------------------------------------------------------------------------
// Block reduce for (sum, sumsq) over 256 threads
// ---------------------------------------------------------------------------
__device__ __forceinline__ void block_reduce2(float& s, float& s2, float* red) {
#pragma unroll
    for (int o = 16; o > 0; o >>= 1) {
        s  += __shfl_xor_sync(0xffffffffu, s,  o);
        s2 += __shfl_xor_sync(0xffffffffu, s2, o);
    }
    int warp = threadIdx.x >> 5, lane = threadIdx.x & 31;
    if (lane == 0) { red[warp] = s; red[8 + warp] = s2; }
    __syncthreads();
    if (warp == 0) {
        float a  = (lane < 8) ? red[lane] : 0.f;
        float a2 = (lane < 8) ? red[8 + lane] : 0.f;
#pragma unroll
        for (int o = 4; o > 0; o >>= 1) {
            a  += __shfl_xor_sync(0xffffffffu, a,  o);
            a2 += __shfl_xor_sync(0xffffffffu, a2, o);
        }
        if (lane == 0) { red[16] = a; red[17] = a2; }
    }
    __syncthreads();
    s = red[16]; s2 = red[17];
}

// ---------------------------------------------------------------------------
// LN1: g_x = fp16_rn( LN( we + per_tag[tag]*mask ) * g + b )
// ---------------------------------------------------------------------------
__global__ void __launch_bounds__(256)
ln1_kernel(const float* __restrict__ we, const int* __restrict__ tags,
           const int* __restrict__ mask,
           const float* __restrict__ g, const float* __restrict__ b) {
    __shared__ float red[18];
    long row = blockIdx.x;
    const float* wr = we + row * HID;
    const float* pr = g_ptag + (long)tags[row] * HID;
    float mk = (float)mask[row];
    int t = threadIdx.x;
    float v[3]; float s = 0.f, s2 = 0.f;
#pragma unroll
    for (int j = 0; j < 3; j++) {
        int c = t + j * 256;
        float val = wr[c] + pr[c] * mk;
        v[j] = val; s += val; s2 += val * val;
    }
    block_reduce2(s, s2, red);
    float mu = s * (1.f / 768.f);
    float var = s2 * (1.f / 768.f) - mu * mu;
    float rs = rsqrtf(var + 1e-12f);
#pragma unroll
    for (int j = 0; j < 3; j++) {
        int c = t + j * 256;
        g_x[row * HID + c] = __float2half_rn((v[j] - mu) * rs * g[c] + b[c]);
    }
}

// ---------------------------------------------------------------------------
// LN2: out = LN(g_ffx) * g + b
// ---------------------------------------------------------------------------
__global__ void __launch_bounds__(256)
ln2_kernel(const float* __restrict__ g, const float* __restrict__ b,
           float* __restrict__ out) {
    __shared__ float red[18];
    long row = blockIdx.x;
    const float* in = g_ffx + row * HID;
    int t = threadIdx.x;
    float v[3]; float s = 0.f, s2 = 0.f;
#pragma unroll
    for (int j = 0; j < 3; j++) {
        int c = t + j * 256;
        float val = in[c];
        v[j] = val; s += val; s2 += val * val;
    }
    block_reduce2(s, s2, red);
    float mu = s * (1.f / 768.f);
    float var = s2 * (1.f / 768.f) - mu * mu;
    float rs = rsqrtf(var + 1e-12f);
#pragma unroll
    for (int j = 0; j < 3; j++) {
        int c = t + j * 256;
        out[row * HID + c] = (v[j] - mu) * rs * g[c] + b[c];
    }
}

// ---------------------------------------------------------------------------
// fp16 mma.sync GEMM, A via smem+ldmatrix, B fragments DIRECT FROM GMEM (L2).
//   MODE 0: A=g_x,  Bt=g_w1t, C=g_h   (half), epi = fp16_rn(relu(acc+bias))
//   MODE 1: A=g_h,  Bt=g_w2t, C=g_ffx (fp32), epi = acc+bias+float(g_x)
// Tile 128x128, 256 threads (8 warps of 64x32), BK=64 halves (128B A rows),
// A: 4-stage cp.async (wait_group<2>), XOR swizzle, ldmatrix.x4.
// B: per-lane half2 LDG (PTX m16n8k16 col fragment: b0=(k=2*tig, n=gid),
//    b1=k+8), 2-step register ping-pong prefetch. 2 CTAs/SM.
// ---------------------------------------------------------------------------
template<int MODE, int N, int K>
__global__ void __launch_bounds__(256, 2)
hgemm_kernel(const float* __restrict__ bias) {
    constexpr int BM = 128, BK = 64;             // BK in halves; 128 B per A row
    constexpr int NS = 4;
    constexpr int ABYTES = BM * BK * 2;          // 16 KB per stage (A only)
    constexpr int KSTEPS = K / 16;               // 48 or 192 k16 steps

    extern __shared__ __align__(16) char smem_raw[];

    const __half* A  = MODE ? g_h   : g_x;
    const __half* Bt = MODE ? g_w2t : g_w1t;

    const int tid = threadIdx.x;
    const int lane = tid & 31;
    const int warp = tid >> 5;
    const int wr = (warp & 1) * 64;              // warp row (0/64)
    const int wc = (warp >> 1) * 32;             // warp col (0..96)
    const long blockRow = (long)blockIdx.y * BM;
    const int  blockCol = blockIdx.x * 128;

    float acc[4][4][4];
#pragma unroll
    for (int mi = 0; mi < 4; mi++)
#pragma unroll
        for (int ni = 0; ni < 4; ni++)
#pragma unroll
            for (int r = 0; r < 4; r++) acc[mi][ni][r] = 0.f;

    const uint32_t sbase = (uint32_t)__cvta_generic_to_shared(smem_raw);

    // A ldmatrix lane mapping (validated R8)
    const int  rA_lane = wr + (lane & 15);
    const uint32_t eA = (uint32_t)(lane >> 4);

    // B direct-gmem fragment base: lane provides n = wc+ni*8+(lane>>2),
    // k = 2*(lane&3) (+8 for b1), advancing 16 halves per k16 step.
    const __half* bwarp =
        Bt + (size_t)(blockCol + wc + (lane >> 2)) * K + (lane & 3) * 2;

    auto ldB = [&](int ks, uint32_t* dst) {
        const __half* p = bwarp + (size_t)ks * 16;
#pragma unroll
        for (int ni = 0; ni < 4; ni++) {
            dst[2 * ni]     = *(const uint32_t*)(p + ni * 8 * K);
            dst[2 * ni + 1] = *(const uint32_t*)(p + ni * 8 * K + 8);
        }
    };

    auto load_tile = [&](int kt, int st) {
        uint32_t base = sbase + (uint32_t)st * ABYTES;
#pragma unroll
        for (int i = 0; i < 4; i++) {
            int idx = tid + i * 256;
            int r = idx >> 3, c = idx & 7;
            const __half* gp = A + (blockRow + r) * (long)K + kt * BK + c * 8;
            cp_async16(base + (uint32_t)(r * 128 + ((c ^ (r & 7)) << 4)), gp);
        }
        cp_commit();
    };

    uint32_t bbuf[2][8];
    ldB(0, bbuf[0]);
    ldB(1, bbuf[1]);

    load_tile(0, 0);
    load_tile(1, 1);
    load_tile(2, 2);

    const int kTiles = K / BK;                   // 12 or 48
    for (int t = 0; t < kTiles; t++) {
        cp_wait<2>();                            // A tile t resident
        __syncthreads();
        if (t + 3 < kTiles) load_tile(t + 3, (t + 3) & 3);
        else cp_commit();                        // keep group arithmetic exact

        const uint32_t sa = sbase + (uint32_t)(t & 3) * ABYTES;
        uint32_t aRow[4], aSwz[4];
#pragma unroll
        for (int mi = 0; mi < 4; mi++) {
            int r = rA_lane + mi * 16;
            aRow[mi] = sa + (uint32_t)(r * 128);
            aSwz[mi] = (uint32_t)(r & 7);
        }
#pragma unroll
        for (int s = 0; s < 4; s++) {            // 4 x k16 steps over BK=64
            const uint32_t cA = (uint32_t)(s * 2) + eA;
            uint32_t af[4][4];
#pragma unroll
            for (int mi = 0; mi < 4; mi++)
                ldsm_x4(af[mi], aRow[mi] + ((cA ^ aSwz[mi]) << 4));
            const uint32_t* bc = bbuf[s & 1];
#pragma unroll
            for (int mi = 0; mi < 4; mi++)
#pragma unroll
                for (int ni = 0; ni < 4; ni++)
                    mma_f16(acc[mi][ni], af[mi], bc[2 * ni], bc[2 * ni + 1]);
            int ksn = 4 * t + s + 2;             // prefetch 2 steps ahead
            if (ksn < KSTEPS) ldB(ksn, bbuf[s & 1]);
        }
    }

    // ---- Epilogue ----
#pragma unroll
    for (int mi = 0; mi < 4; mi++) {
#pragma unroll
        for (int ri = 0; ri < 2; ri++) {
            long row = blockRow + wr + mi * 16 + (lane >> 2) + ri * 8;
#pragma unroll
            for (int ni = 0; ni < 4; ni++) {
                int col = blockCol + wc + ni * 8 + (lane & 3) * 2;
                float v0 = acc[mi][ni][ri * 2 + 0] + bias[col];
                float v1 = acc[mi][ni][ri * 2 + 1] + bias[col + 1];
                if (MODE == 0) {
                    __half2 h2;
                    h2.x = __float2half_rn(fmaxf(v0, 0.f));
                    h2.y = __float2half_rn(fmaxf(v1, 0.f));
                    *(__half2*)(g_h + row * (long)N + col) = h2;
                } else {
                    __half2 x2 = *(const __half2*)(g_x + row * HID + col);
                    float2 o;
                    o.x = v0 + __half2float(x2.x);
                    o.y = v1 + __half2float(x2.y);
                    *(float2*)(g_ffx + row * (long)N + col) = o;
                }
            }
        }
    }
}

// ---------------------------------------------------------------------------
// Launch  (order keeps gemm1 at the ncu-captured slot #4)
// ---------------------------------------------------------------------------
extern "C" void kernel_launch(void* const* d_in, const int* in_sizes, int n_in,
                              void* d_out, int out_size) {
    const float* we      = (const float*)d_in[0];
    const int*   tags    = (const int*)d_in[1];
    const int*   mask    = (const int*)d_in[2];
    const float* tag_emb = (const float*)d_in[3];
    const float* Wv      = (const float*)d_in[4];
    const float* bv      = (const float*)d_in[5];
    const float* Wo      = (const float*)d_in[6];
    const float* bo      = (const float*)d_in[7];
    const float* ln1g    = (const float*)d_in[8];
    const float* ln1b    = (const float*)d_in[9];
    const float* W1      = (const float*)d_in[10];
    const float* b1      = (const float*)d_in[11];
    const float* W2      = (const float*)d_in[12];
    const float* b2      = (const float*)d_in[13];
    const float* ln2g    = (const float*)d_in[14];
    const float* ln2b    = (const float*)d_in[15];
    float* out = (float*)d_out;

    const int smem_bytes = 4 * 128 * 64 * 2;     // 65536 B (A stages only)
    cudaFuncSetAttribute(hgemm_kernel<0, INTR, HID>,
                         cudaFuncAttributeMaxDynamicSharedMemorySize, smem_bytes);
    cudaFuncSetAttribute(hgemm_kernel<1, HID, INTR>,
                         cudaFuncAttributeMaxDynamicSharedMemorySize, smem_bytes);

    prep_kernel<0, HID, INTR><<<2304 + 192, 256>>>(W1, tag_emb, Wv, bv);
    prep_kernel<1, INTR, HID><<<2304 + 192, 256>>>(W2, nullptr, Wo, bo);

    ln1_kernel<<<TOKENS, 256>>>(we, tags, mask, ln1g, ln1b);

    hgemm_kernel<0, INTR, HID>
        <<<dim3(INTR / 128, TOKENS / 128), 256, smem_bytes>>>(b1);

    hgemm_kernel<1, HID, INTR>
        <<<dim3(HID / 128, TOKENS / 128), 256, smem_bytes>>>(b2);

    ln2_kernel<<<TOKENS, 256>>>(ln2g, ln2b, out);
}

// round 10
// speedup vs baseline: 1.5262x; 1.5262x over previous
#include <cuda_runtime.h>
#include <cuda_fp16.h>
#include <cstdint>

#define TOKENS 32768
#define HID 768
#define INTR 3072
#define NTAGS 64

// ---------------------------------------------------------------------------
// Scratch (static device memory — allocation-free per harness rules)
// ---------------------------------------------------------------------------
__device__ __align__(256) __half g_x[(size_t)TOKENS * HID];    // LN1 out (fp16)
__device__ __align__(256) __half g_h[(size_t)TOKENS * INTR];   // relu(x@W1+b1) fp16
__device__ __align__(256) float  g_ffx[(size_t)TOKENS * HID];  // ff + x (fp32)
__device__ __align__(256) __half g_w1t[(size_t)INTR * HID];    // W1^T [n][k] fp16
__device__ __align__(256) __half g_w2t[(size_t)HID * INTR];    // W2^T [n][k] fp16
__device__ __align__(256) float  g_tmp[NTAGS * HID];           // tag_emb@Wv+bv
__device__ __align__(256) float  g_ptag[NTAGS * HID];          // per-tag vector

// ---------------------------------------------------------------------------
// Helpers
// ---------------------------------------------------------------------------
__device__ __forceinline__ void cp_async16(uint32_t saddr, const void* gaddr) {
    asm volatile("cp.async.cg.shared.global [%0], [%1], 16;" :: "r"(saddr), "l"(gaddr));
}
__device__ __forceinline__ void cp_commit() { asm volatile("cp.async.commit_group;"); }
template<int N> __device__ __forceinline__ void cp_wait() {
    asm volatile("cp.async.wait_group %0;" :: "n"(N));
}

__device__ __forceinline__ void mma_f16(float c[4], const uint32_t a[4],
                                        uint32_t b0, uint32_t b1) {
    asm volatile(
        "mma.sync.aligned.m16n8k16.row.col.f32.f16.f16.f32 "
        "{%0,%1,%2,%3}, {%4,%5,%6,%7}, {%8,%9}, {%0,%1,%2,%3};"
        : "+f"(c[0]), "+f"(c[1]), "+f"(c[2]), "+f"(c[3])
        : "r"(a[0]), "r"(a[1]), "r"(a[2]), "r"(a[3]), "r"(b0), "r"(b1));
}

__device__ __forceinline__ void ldsm_x4(uint32_t r[4], uint32_t addr) {
    asm volatile("ldmatrix.sync.aligned.m8n8.x4.shared.b16 {%0,%1,%2,%3}, [%4];"
        : "=r"(r[0]), "=r"(r[1]), "=r"(r[2]), "=r"(r[3]) : "r"(addr));
}

// ---------------------------------------------------------------------------
// Fused prep kernel: weight transpose+round -> half [n][k], plus tag GEMV tail
// ---------------------------------------------------------------------------
template<int WHICH, int K, int N>
__global__ void __launch_bounds__(256)
prep_kernel(const float* __restrict__ W,
            const float* __restrict__ E,
            const float* __restrict__ Wt,
            const float* __restrict__ bt) {
    __shared__ float sbuf[32 * 33];
    constexpr int TB = (N / 32) * (K / 32);
    const int tid = threadIdx.x;
    const int bid = blockIdx.x;

    if (bid < TB) {
        int nb = bid % (N / 32), kb = bid / (N / 32);
        int tx = tid & 31, ty = tid >> 5;
        float (*tile)[33] = (float(*)[33])sbuf;
#pragma unroll
        for (int i = ty; i < 32; i += 8)
            tile[i][tx] = W[(long)(kb * 32 + i) * N + nb * 32 + tx];
        __syncthreads();
        __half* out = WHICH ? g_w2t : g_w1t;
#pragma unroll
        for (int i = ty; i < 32; i += 8)
            out[(long)(nb * 32 + i) * K + kb * 32 + tx] = __float2half_rn(tile[tx][i]);
    } else {
        int b2 = bid - TB;
        int t = b2 / 3, chunk = b2 - t * 3;
        int n = chunk * 256 + tid;
        const float* Es = WHICH ? g_tmp : E;
        float* O = WHICH ? g_ptag : g_tmp;
        for (int c = tid; c < HID; c += 256) sbuf[c] = Es[t * HID + c];
        __syncthreads();
        float a0 = bt[n], a1 = 0.f, a2 = 0.f, a3 = 0.f;
        for (int k = 0; k < HID; k += 8) {
            float w0 = Wt[(long)(k + 0) * HID + n];
            float w1 = Wt[(long)(k + 1) * HID + n];
            float w2 = Wt[(long)(k + 2) * HID + n];
            float w3 = Wt[(long)(k + 3) * HID + n];
            float w4 = Wt[(long)(k + 4) * HID + n];
            float w5 = Wt[(long)(k + 5) * HID + n];
            float w6 = Wt[(long)(k + 6) * HID + n];
            float w7 = Wt[(long)(k + 7) * HID + n];
            a0 = fmaf(sbuf[k + 0], w0, a0);
            a1 = fmaf(sbuf[k + 1], w1, a1);
            a2 = fmaf(sbuf[k + 2], w2, a2);
            a3 = fmaf(sbuf[k + 3], w3, a3);
            a0 = fmaf(sbuf[k + 4], w4, a0);
            a1 = fmaf(sbuf[k + 5], w5, a1);
            a2 = fmaf(sbuf[k + 6], w6, a2);
            a3 = fmaf(sbuf[k + 7], w7, a3);
        }
        O[t * HID + n] = (a0 + a1) + (a2 + a3);
    }
}

// ---------------------------------------------------------------------------
// Block reduce for (sum, sumsq) over 256 threads
// ---------------------------------------------------------------------------
__device__ __forceinline__ void block_reduce2(float& s, float& s2, float* red) {
#pragma unroll
    for (int o = 16; o > 0; o >>= 1) {
        s  += __shfl_xor_sync(0xffffffffu, s,  o);
        s2 += __shfl_xor_sync(0xffffffffu, s2, o);
    }
    int warp = threadIdx.x >> 5, lane = threadIdx.x & 31;
    if (lane == 0) { red[warp] = s; red[8 + warp] = s2; }
    __syncthreads();
    if (warp == 0) {
        float a  = (lane < 8) ? red[lane] : 0.f;
        float a2 = (lane < 8) ? red[8 + lane] : 0.f;
#pragma unroll
        for (int o = 4; o > 0; o >>= 1) {
            a  += __shfl_xor_sync(0xffffffffu, a,  o);
            a2 += __shfl_xor_sync(0xffffffffu, a2, o);
        }
        if (lane == 0) { red[16] = a; red[17] = a2; }
    }
    __syncthreads();
    s = red[16]; s2 = red[17];
}

// ---------------------------------------------------------------------------
// LN1: g_x = fp16_rn( LN( we + per_tag[tag]*mask ) * g + b )
// ---------------------------------------------------------------------------
__global__ void __launch_bounds__(256)
ln1_kernel(const float* __restrict__ we, const int* __restrict__ tags,
           const int* __restrict__ mask,
           const float* __restrict__ g, const float* __restrict__ b) {
    __shared__ float red[18];
    long row = blockIdx.x;
    const float* wr = we + row * HID;
    const float* pr = g_ptag + (long)tags[row] * HID;
    float mk = (float)mask[row];
    int t = threadIdx.x;
    float v[3]; float s = 0.f, s2 = 0.f;
#pragma unroll
    for (int j = 0; j < 3; j++) {
        int c = t + j * 256;
        float val = wr[c] + pr[c] * mk;
        v[j] = val; s += val; s2 += val * val;
    }
    block_reduce2(s, s2, red);
    float mu = s * (1.f / 768.f);
    float var = s2 * (1.f / 768.f) - mu * mu;
    float rs = rsqrtf(var + 1e-12f);
#pragma unroll
    for (int j = 0; j < 3; j++) {
        int c = t + j * 256;
        g_x[row * HID + c] = __float2half_rn((v[j] - mu) * rs * g[c] + b[c]);
    }
}

// ---------------------------------------------------------------------------
// LN2: out = LN(g_ffx) * g + b
// ---------------------------------------------------------------------------
__global__ void __launch_bounds__(256)
ln2_kernel(const float* __restrict__ g, const float* __restrict__ b,
           float* __restrict__ out) {
    __shared__ float red[18];
    long row = blockIdx.x;
    const float* in = g_ffx + row * HID;
    int t = threadIdx.x;
    float v[3]; float s = 0.f, s2 = 0.f;
#pragma unroll
    for (int j = 0; j < 3; j++) {
        int c = t + j * 256;
        float val = in[c];
        v[j] = val; s += val; s2 += val * val;
    }
    block_reduce2(s, s2, red);
    float mu = s * (1.f / 768.f);
    float var = s2 * (1.f / 768.f) - mu * mu;
    float rs = rsqrtf(var + 1e-12f);
#pragma unroll
    for (int j = 0; j < 3; j++) {
        int c = t + j * 256;
        out[row * HID + c] = (v[j] - mu) * rs * g[c] + b[c];
    }
}

// ---------------------------------------------------------------------------
// fp16 mma.sync GEMM, 128x256 CTA tile, 8 warps of 64x64 (2 row x 4 col).
//   MODE 0: A=g_x,  Bt=g_w1t, C=g_h   (half), epi = fp16_rn(relu(acc+bias))
//   MODE 1: A=g_h,  Bt=g_w2t, C=g_ffx (fp32), epi = acc+bias+float(g_x)
// BK=64 halves (128B rows), XOR swizzle, ldmatrix.x4 for A and B,
// 4-stage cp.async (wait_group<2>), 1 CTA/SM (acc-register heavy).
// Rationale: MMA:LDSM ratio 4:1 (vs 2.67:1 at 64x32 warps) cuts smem reads
// per output by 1.5x -- smem crossbar was the R8 binder (L1=62%, tensor=65%).
// ---------------------------------------------------------------------------
template<int MODE, int N, int K>
__global__ void __launch_bounds__(256, 1)
hgemm_kernel(const float* __restrict__ bias) {
    constexpr int BM = 128, BN = 256, BK = 64;   // BK in halves; 128 B per row
    constexpr int ABYTES = BM * BK * 2;          // 16 KB
    constexpr int BBYTES = BN * BK * 2;          // 32 KB
    constexpr int STG = ABYTES + BBYTES;         // 48 KB per stage

    extern __shared__ __align__(16) char smem_raw[];

    const __half* A  = MODE ? g_h   : g_x;
    const __half* Bt = MODE ? g_w2t : g_w1t;

    const int tid = threadIdx.x;
    const int lane = tid & 31;
    const int warp = tid >> 5;
    const int wr = (warp & 1) * 64;              // warp row (0/64)
    const int wc = (warp >> 1) * 64;             // warp col (0/64/128/192)
    const long blockRow = (long)blockIdx.y * BM;
    const int  blockCol = blockIdx.x * BN;

    float acc[4][8][4];
#pragma unroll
    for (int mi = 0; mi < 4; mi++)
#pragma unroll
        for (int ni = 0; ni < 8; ni++)
#pragma unroll
            for (int r = 0; r < 4; r++) acc[mi][ni][r] = 0.f;

    const uint32_t sbase = (uint32_t)__cvta_generic_to_shared(smem_raw);

    // ldmatrix lane mappings (validated in R8)
    const int  rA_lane = wr + (lane & 15);
    const uint32_t eA = (uint32_t)(lane >> 4);
    const int  rB_lane = wc + ((lane & 16) >> 1) + (lane & 7);
    const uint32_t eB = (uint32_t)((lane >> 3) & 1);

    auto load_tile = [&](int kt, int st) {
        uint32_t base = sbase + (uint32_t)st * STG;
        // A: 128 rows x 8 chunks = 1024 -> 4/thread
#pragma unroll
        for (int i = 0; i < 4; i++) {
            int idx = tid + i * 256;
            int r = idx >> 3, c = idx & 7;
            const __half* gp = A + (blockRow + r) * (long)K + kt * BK + c * 8;
            cp_async16(base + (uint32_t)(r * 128 + ((c ^ (r & 7)) << 4)), gp);
        }
        // B: 256 n-rows x 8 chunks = 2048 -> 8/thread
#pragma unroll
        for (int i = 0; i < 8; i++) {
            int idx = tid + i * 256;
            int r = idx >> 3, c = idx & 7;
            const __half* gp = Bt + (long)(blockCol + r) * K + kt * BK + c * 8;
            cp_async16(base + ABYTES + (uint32_t)(r * 128 + ((c ^ (r & 7)) << 4)), gp);
        }
        cp_commit();
    };

    load_tile(0, 0);
    load_tile(1, 1);
    load_tile(2, 2);

    const int kTiles = K / BK;                   // 12 or 48
    for (int t = 0; t < kTiles; t++) {
        cp_wait<2>();                            // tile t resident
        __syncthreads();                         // all warps done with stage being reused
        if (t + 3 < kTiles) load_tile(t + 3, (t + 3) & 3);
        else cp_commit();                        // keep group arithmetic exact

        const uint32_t sa = sbase + (uint32_t)(t & 3) * STG;
        const uint32_t sb = sa + ABYTES;
        uint32_t aRow[4], aSwz[4], bRow[4], bSwz[4];
#pragma unroll
        for (int mi = 0; mi < 4; mi++) {
            int r = rA_lane + mi * 16;
            aRow[mi] = sa + (uint32_t)(r * 128);
            aSwz[mi] = (uint32_t)(r & 7);
        }
#pragma unroll
        for (int p = 0; p < 4; p++) {
            int r = rB_lane + p * 16;
            bRow[p] = sb + (uint32_t)(r * 128);
            bSwz[p] = (uint32_t)(r & 7);
        }
#pragma unroll
        for (int s = 0; s < 4; s++) {            // 4 x k16 steps over BK=64
            const uint32_t cA = (uint32_t)(s * 2) + eA;
            const uint32_t cB = (uint32_t)(s * 2) + eB;
            uint32_t af[4][4], bf[4][4];
#pragma unroll
            for (int mi = 0; mi < 4; mi++)
                ldsm_x4(af[mi], aRow[mi] + ((cA ^ aSwz[mi]) << 4));
#pragma unroll
            for (int p = 0; p < 4; p++)
                ldsm_x4(bf[p], bRow[p] + ((cB ^ bSwz[p]) << 4));
#pragma unroll
            for (int mi = 0; mi < 4; mi++) {
#pragma unroll
                for (int p = 0; p < 4; p++) {
                    mma_f16(acc[mi][2 * p + 0], af[mi], bf[p][0], bf[p][1]);
                    mma_f16(acc[mi][2 * p + 1], af[mi], bf[p][2], bf[p][3]);
                }
            }
        }
    }

    // ---- Epilogue ----
#pragma unroll
    for (int mi = 0; mi < 4; mi++) {
#pragma unroll
        for (int ri = 0; ri < 2; ri++) {
            long row = blockRow + wr + mi * 16 + (lane >> 2) + ri * 8;
#pragma unroll
            for (int ni = 0; ni < 8; ni++) {
                int col = blockCol + wc + ni * 8 + (lane & 3) * 2;
                float v0 = acc[mi][ni][ri * 2 + 0] + bias[col];
                float v1 = acc[mi][ni][ri * 2 + 1] + bias[col + 1];
                if (MODE == 0) {
                    __half2 h2;
                    h2.x = __float2half_rn(fmaxf(v0, 0.f));
                    h2.y = __float2half_rn(fmaxf(v1, 0.f));
                    *(__half2*)(g_h + row * (long)N + col) = h2;
                } else {
                    __half2 x2 = *(const __half2*)(g_x + row * HID + col);
                    float2 o;
                    o.x = v0 + __half2float(x2.x);
                    o.y = v1 + __half2float(x2.y);
                    *(float2*)(g_ffx + row * (long)N + col) = o;
                }
            }
        }
    }
}

// ---------------------------------------------------------------------------
// Launch  (order keeps gemm1 at the ncu-captured slot #4)
// ---------------------------------------------------------------------------
extern "C" void kernel_launch(void* const* d_in, const int* in_sizes, int n_in,
                              void* d_out, int out_size) {
    const float* we      = (const float*)d_in[0];
    const int*   tags    = (const int*)d_in[1];
    const int*   mask    = (const int*)d_in[2];
    const float* tag_emb = (const float*)d_in[3];
    const float* Wv      = (const float*)d_in[4];
    const float* bv      = (const float*)d_in[5];
    const float* Wo      = (const float*)d_in[6];
    const float* bo      = (const float*)d_in[7];
    const float* ln1g    = (const float*)d_in[8];
    const float* ln1b    = (const float*)d_in[9];
    const float* W1      = (const float*)d_in[10];
    const float* b1      = (const float*)d_in[11];
    const float* W2      = (const float*)d_in[12];
    const float* b2      = (const float*)d_in[13];
    const float* ln2g    = (const float*)d_in[14];
    const float* ln2b    = (const float*)d_in[15];
    float* out = (float*)d_out;

    const int smem_bytes = 4 * (128 * 64 * 2 + 256 * 64 * 2);   // 196608 B
    cudaFuncSetAttribute(hgemm_kernel<0, INTR, HID>,
                         cudaFuncAttributeMaxDynamicSharedMemorySize, smem_bytes);
    cudaFuncSetAttribute(hgemm_kernel<1, HID, INTR>,
                         cudaFuncAttributeMaxDynamicSharedMemorySize, smem_bytes);

    prep_kernel<0, HID, INTR><<<2304 + 192, 256>>>(W1, tag_emb, Wv, bv);
    prep_kernel<1, INTR, HID><<<2304 + 192, 256>>>(W2, nullptr, Wo, bo);

    ln1_kernel<<<TOKENS, 256>>>(we, tags, mask, ln1g, ln1b);

    hgemm_kernel<0, INTR, HID>
        <<<dim3(INTR / 256, TOKENS / 128), 256, smem_bytes>>>(b1);

    hgemm_kernel<1, HID, INTR>
        <<<dim3(HID / 256, TOKENS / 128), 256, smem_bytes>>>(b2);

    ln2_kernel<<<TOKENS, 256>>>(ln2g, ln2b, out);
}

// round 11
// speedup vs baseline: 1.6367x; 1.0724x over previous
#include <cuda_runtime.h>
#include <cuda_fp16.h>
#include <cstdint>

#define TOKENS 32768
#define HID 768
#define INTR 3072
#define NTAGS 64

// ---------------------------------------------------------------------------
// Scratch (static device memory — allocation-free per harness rules)
// ---------------------------------------------------------------------------
__device__ __align__(256) __half g_x[(size_t)TOKENS * HID];    // LN1 out (fp16)
__device__ __align__(256) __half g_h[(size_t)TOKENS * INTR];   // relu(x@W1+b1) fp16
__device__ __align__(256) float  g_ffx[(size_t)TOKENS * HID];  // ff + x (fp32)
__device__ __align__(256) __half g_w1t[(size_t)INTR * HID];    // W1^T [n][k] fp16
__device__ __align__(256) __half g_w2t[(size_t)HID * INTR];    // W2^T [n][k] fp16
__device__ __align__(256) float  g_tmp[NTAGS * HID];           // tag_emb@Wv+bv
__device__ __align__(256) float  g_ptag[NTAGS * HID];          // per-tag vector

// ---------------------------------------------------------------------------
// Helpers
// ---------------------------------------------------------------------------
__device__ __forceinline__ void cp_async16(uint32_t saddr, const void* gaddr) {
    asm volatile("cp.async.cg.shared.global [%0], [%1], 16;" :: "r"(saddr), "l"(gaddr));
}
__device__ __forceinline__ void cp_commit() { asm volatile("cp.async.commit_group;"); }
template<int N> __device__ __forceinline__ void cp_wait() {
    asm volatile("cp.async.wait_group %0;" :: "n"(N));
}

__device__ __forceinline__ void mma_f16(float c[4], const uint32_t a[4],
                                        uint32_t b0, uint32_t b1) {
    asm volatile(
        "mma.sync.aligned.m16n8k16.row.col.f32.f16.f16.f32 "
        "{%0,%1,%2,%3}, {%4,%5,%6,%7}, {%8,%9}, {%0,%1,%2,%3};"
        : "+f"(c[0]), "+f"(c[1]), "+f"(c[2]), "+f"(c[3])
        : "r"(a[0]), "r"(a[1]), "r"(a[2]), "r"(a[3]), "r"(b0), "r"(b1));
}

__device__ __forceinline__ void ldsm_x4(uint32_t r[4], uint32_t addr) {
    asm volatile("ldmatrix.sync.aligned.m8n8.x4.shared.b16 {%0,%1,%2,%3}, [%4];"
        : "=r"(r[0]), "=r"(r[1]), "=r"(r[2]), "=r"(r[3]) : "r"(addr));
}

// ---------------------------------------------------------------------------
// Fused prep kernel: weight transpose+round -> half [n][k], plus tag GEMV tail
// ---------------------------------------------------------------------------
template<int WHICH, int K, int N>
__global__ void __launch_bounds__(256)
prep_kernel(const float* __restrict__ W,
            const float* __restrict__ E,
            const float* __restrict__ Wt,
            const float* __restrict__ bt) {
    __shared__ float sbuf[32 * 33];
    constexpr int TB = (N / 32) * (K / 32);
    const int tid = threadIdx.x;
    const int bid = blockIdx.x;

    if (bid < TB) {
        int nb = bid % (N / 32), kb = bid / (N / 32);
        int tx = tid & 31, ty = tid >> 5;
        float (*tile)[33] = (float(*)[33])sbuf;
#pragma unroll
        for (int i = ty; i < 32; i += 8)
            tile[i][tx] = W[(long)(kb * 32 + i) * N + nb * 32 + tx];
        __syncthreads();
        __half* out = WHICH ? g_w2t : g_w1t;
#pragma unroll
        for (int i = ty; i < 32; i += 8)
            out[(long)(nb * 32 + i) * K + kb * 32 + tx] = __float2half_rn(tile[tx][i]);
    } else {
        int b2 = bid - TB;
        int t = b2 / 3, chunk = b2 - t * 3;
        int n = chunk * 256 + tid;
        const float* Es = WHICH ? g_tmp : E;
        float* O = WHICH ? g_ptag : g_tmp;
        for (int c = tid; c < HID; c += 256) sbuf[c] = Es[t * HID + c];
        __syncthreads();
        float a0 = bt[n], a1 = 0.f, a2 = 0.f, a3 = 0.f;
        for (int k = 0; k < HID; k += 8) {
            float w0 = Wt[(long)(k + 0) * HID + n];
            float w1 = Wt[(long)(k + 1) * HID + n];
            float w2 = Wt[(long)(k + 2) * HID + n];
            float w3 = Wt[(long)(k + 3) * HID + n];
            float w4 = Wt[(long)(k + 4) * HID + n];
            float w5 = Wt[(long)(k + 5) * HID + n];
            float w6 = Wt[(long)(k + 6) * HID + n];
            float w7 = Wt[(long)(k + 7) * HID + n];
            a0 = fmaf(sbuf[k + 0], w0, a0);
            a1 = fmaf(sbuf[k + 1], w1, a1);
            a2 = fmaf(sbuf[k + 2], w2, a2);
            a3 = fmaf(sbuf[k + 3], w3, a3);
            a0 = fmaf(sbuf[k + 4], w4, a0);
            a1 = fmaf(sbuf[k + 5], w5, a1);
            a2 = fmaf(sbuf[k + 6], w6, a2);
            a3 = fmaf(sbuf[k + 7], w7, a3);
        }
        O[t * HID + n] = (a0 + a1) + (a2 + a3);
    }
}

// ---------------------------------------------------------------------------
// Block reduce for (sum, sumsq) over 256 threads
// ---------------------------------------------------------------------------
__device__ __forceinline__ void block_reduce2(float& s, float& s2, float* red) {
#pragma unroll
    for (int o = 16; o > 0; o >>= 1) {
        s  += __shfl_xor_sync(0xffffffffu, s,  o);
        s2 += __shfl_xor_sync(0xffffffffu, s2, o);
    }
    int warp = threadIdx.x >> 5, lane = threadIdx.x & 31;
    if (lane == 0) { red[warp] = s; red[8 + warp] = s2; }
    __syncthreads();
    if (warp == 0) {
        float a  = (lane < 8) ? red[lane] : 0.f;
        float a2 = (lane < 8) ? red[8 + lane] : 0.f;
#pragma unroll
        for (int o = 4; o > 0; o >>= 1) {
            a  += __shfl_xor_sync(0xffffffffu, a,  o);
            a2 += __shfl_xor_sync(0xffffffffu, a2, o);
        }
        if (lane == 0) { red[16] = a; red[17] = a2; }
    }
    __syncthreads();
    s = red[16]; s2 = red[17];
}

// ---------------------------------------------------------------------------
// LN1: g_x = fp16_rn( LN( we + per_tag[tag]*mask ) * g + b )
// ---------------------------------------------------------------------------
__global__ void __launch_bounds__(256)
ln1_kernel(const float* __restrict__ we, const int* __restrict__ tags,
           const int* __restrict__ mask,
           const float* __restrict__ g, const float* __restrict__ b) {
    __shared__ float red[18];
    long row = blockIdx.x;
    const float* wr = we + row * HID;
    const float* pr = g_ptag + (long)tags[row] * HID;
    float mk = (float)mask[row];
    int t = threadIdx.x;
    float v[3]; float s = 0.f, s2 = 0.f;
#pragma unroll
    for (int j = 0; j < 3; j++) {
        int c = t + j * 256;
        float val = wr[c] + pr[c] * mk;
        v[j] = val; s += val; s2 += val * val;
    }
    block_reduce2(s, s2, red);
    float mu = s * (1.f / 768.f);
    float var = s2 * (1.f / 768.f) - mu * mu;
    float rs = rsqrtf(var + 1e-12f);
#pragma unroll
    for (int j = 0; j < 3; j++) {
        int c = t + j * 256;
        g_x[row * HID + c] = __float2half_rn((v[j] - mu) * rs * g[c] + b[c]);
    }
}

// ---------------------------------------------------------------------------
// LN2: out = LN(g_ffx) * g + b
// ---------------------------------------------------------------------------
__global__ void __launch_bounds__(256)
ln2_kernel(const float* __restrict__ g, const float* __restrict__ b,
           float* __restrict__ out) {
    __shared__ float red[18];
    long row = blockIdx.x;
    const float* in = g_ffx + row * HID;
    int t = threadIdx.x;
    float v[3]; float s = 0.f, s2 = 0.f;
#pragma unroll
    for (int j = 0; j < 3; j++) {
        int c = t + j * 256;
        float val = in[c];
        v[j] = val; s += val; s2 += val * val;
    }
    block_reduce2(s, s2, red);
    float mu = s * (1.f / 768.f);
    float var = s2 * (1.f / 768.f) - mu * mu;
    float rs = rsqrtf(var + 1e-12f);
#pragma unroll
    for (int j = 0; j < 3; j++) {
        int c = t + j * 256;
        out[row * HID + c] = (v[j] - mu) * rs * g[c] + b[c];
    }
}

// ---------------------------------------------------------------------------
// fp16 mma.sync GEMM: 128x128 CTA tile, 128 threads = 4 warps of 64x64 (2x2).
//   MODE 0: A=g_x,  Bt=g_w1t, C=g_h   (half), epi = fp16_rn(relu(acc+bias))
//   MODE 1: A=g_h,  Bt=g_w2t, C=g_ffx (fp32), epi = acc+bias+float(g_x)
// BK=64 halves (128B rows), XOR swizzle, ldmatrix.x4, NS=2 double buffer
// (wait_group<0> + sync, then load t+1 / compute t).
// __launch_bounds__(128, 3): reg cap 170 -> 3 CTAs/SM = 12 warps with the
// 64x64 warp tile's 1.8x per-warp efficiency (R10 measurement), and three
// independent barrier domains instead of one.
// ---------------------------------------------------------------------------
template<int MODE, int N, int K>
__global__ void __launch_bounds__(128, 3)
hgemm_kernel(const float* __restrict__ bias) {
    constexpr int BM = 128, BK = 64;             // BK in halves; 128 B per row
    constexpr int ABYTES = BM * BK * 2;          // 16 KB
    constexpr int STG = 2 * ABYTES;              // A + B = 32 KB per stage

    extern __shared__ __align__(16) char smem_raw[];

    const __half* A  = MODE ? g_h   : g_x;
    const __half* Bt = MODE ? g_w2t : g_w1t;

    const int tid = threadIdx.x;
    const int lane = tid & 31;
    const int warp = tid >> 5;                   // 0..3
    const int wr = (warp & 1) * 64;              // warp row (0/64)
    const int wc = (warp >> 1) * 64;             // warp col (0/64)
    const long blockRow = (long)blockIdx.y * BM;
    const int  blockCol = blockIdx.x * 128;

    float acc[4][8][4];
#pragma unroll
    for (int mi = 0; mi < 4; mi++)
#pragma unroll
        for (int ni = 0; ni < 8; ni++)
#pragma unroll
            for (int r = 0; r < 4; r++) acc[mi][ni][r] = 0.f;

    const uint32_t sbase = (uint32_t)__cvta_generic_to_shared(smem_raw);

    // ldmatrix lane mappings (validated R8/R10)
    const int  rA_lane = wr + (lane & 15);
    const uint32_t eA = (uint32_t)(lane >> 4);
    const int  rB_lane = wc + ((lane & 16) >> 1) + (lane & 7);
    const uint32_t eB = (uint32_t)((lane >> 3) & 1);

    auto load_tile = [&](int kt, int st) {
        uint32_t base = sbase + (uint32_t)st * STG;
        // A: 128 rows x 8 chunks = 1024 -> 8 per thread (128 threads)
#pragma unroll
        for (int i = 0; i < 8; i++) {
            int idx = tid + i * 128;
            int r = idx >> 3, c = idx & 7;
            const __half* gp = A + (blockRow + r) * (long)K + kt * BK + c * 8;
            cp_async16(base + (uint32_t)(r * 128 + ((c ^ (r & 7)) << 4)), gp);
        }
        // B: 128 n-rows x 8 chunks = 1024 -> 8 per thread
#pragma unroll
        for (int i = 0; i < 8; i++) {
            int idx = tid + i * 128;
            int r = idx >> 3, c = idx & 7;
            const __half* gp = Bt + (long)(blockCol + r) * K + kt * BK + c * 8;
            cp_async16(base + ABYTES + (uint32_t)(r * 128 + ((c ^ (r & 7)) << 4)), gp);
        }
        cp_commit();
    };

    load_tile(0, 0);

    const int kTiles = K / BK;                   // 12 or 48
    for (int t = 0; t < kTiles; t++) {
        cp_wait<0>();                            // tile t resident (all groups)
        __syncthreads();                         // writes visible; laggards done
        if (t + 1 < kTiles) load_tile(t + 1, (t + 1) & 1);

        const uint32_t sa = sbase + (uint32_t)(t & 1) * STG;
        const uint32_t sb = sa + ABYTES;
        uint32_t aRow[4], aSwz[4], bRow[4], bSwz[4];
#pragma unroll
        for (int mi = 0; mi < 4; mi++) {
            int r = rA_lane + mi * 16;
            aRow[mi] = sa + (uint32_t)(r * 128);
            aSwz[mi] = (uint32_t)(r & 7);
        }
#pragma unroll
        for (int p = 0; p < 4; p++) {
            int r = rB_lane + p * 16;
            bRow[p] = sb + (uint32_t)(r * 128);
            bSwz[p] = (uint32_t)(r & 7);
        }
#pragma unroll
        for (int s = 0; s < 4; s++) {            // 4 x k16 steps over BK=64
            const uint32_t cA = (uint32_t)(s * 2) + eA;
            const uint32_t cB = (uint32_t)(s * 2) + eB;
            uint32_t af[4][4], bf[4][4];
#pragma unroll
            for (int mi = 0; mi < 4; mi++)
                ldsm_x4(af[mi], aRow[mi] + ((cA ^ aSwz[mi]) << 4));
#pragma unroll
            for (int p = 0; p < 4; p++)
                ldsm_x4(bf[p], bRow[p] + ((cB ^ bSwz[p]) << 4));
#pragma unroll
            for (int mi = 0; mi < 4; mi++) {
#pragma unroll
                for (int p = 0; p < 4; p++) {
                    mma_f16(acc[mi][2 * p + 0], af[mi], bf[p][0], bf[p][1]);
                    mma_f16(acc[mi][2 * p + 1], af[mi], bf[p][2], bf[p][3]);
                }
            }
        }
        __syncthreads();                         // all warps done with stage t&1
    }

    // ---- Epilogue ----
#pragma unroll
    for (int mi = 0; mi < 4; mi++) {
#pragma unroll
        for (int ri = 0; ri < 2; ri++) {
            long row = blockRow + wr + mi * 16 + (lane >> 2) + ri * 8;
#pragma unroll
            for (int ni = 0; ni < 8; ni++) {
                int col = blockCol + wc + ni * 8 + (lane & 3) * 2;
                float v0 = acc[mi][ni][ri * 2 + 0] + bias[col];
                float v1 = acc[mi][ni][ri * 2 + 1] + bias[col + 1];
                if (MODE == 0) {
                    __half2 h2;
                    h2.x = __float2half_rn(fmaxf(v0, 0.f));
                    h2.y = __float2half_rn(fmaxf(v1, 0.f));
                    *(__half2*)(g_h + row * (long)N + col) = h2;
                } else {
                    __half2 x2 = *(const __half2*)(g_x + row * HID + col);
                    float2 o;
                    o.x = v0 + __half2float(x2.x);
                    o.y = v1 + __half2float(x2.y);
                    *(float2*)(g_ffx + row * (long)N + col) = o;
                }
            }
        }
    }
}

// ---------------------------------------------------------------------------
// Launch  (order keeps gemm1 at the ncu-captured slot #4)
// ---------------------------------------------------------------------------
extern "C" void kernel_launch(void* const* d_in, const int* in_sizes, int n_in,
                              void* d_out, int out_size) {
    const float* we      = (const float*)d_in[0];
    const int*   tags    = (const int*)d_in[1];
    const int*   mask    = (const int*)d_in[2];
    const float* tag_emb = (const float*)d_in[3];
    const float* Wv      = (const float*)d_in[4];
    const float* bv      = (const float*)d_in[5];
    const float* Wo      = (const float*)d_in[6];
    const float* bo      = (const float*)d_in[7];
    const float* ln1g    = (const float*)d_in[8];
    const float* ln1b    = (const float*)d_in[9];
    const float* W1      = (const float*)d_in[10];
    const float* b1      = (const float*)d_in[11];
    const float* W2      = (const float*)d_in[12];
    const float* b2      = (const float*)d_in[13];
    const float* ln2g    = (const float*)d_in[14];
    const float* ln2b    = (const float*)d_in[15];
    float* out = (float*)d_out;

    const int smem_bytes = 2 * 2 * 128 * 64 * 2;   // 65536 B (2 stages x 32 KB)
    cudaFuncSetAttribute(hgemm_kernel<0, INTR, HID>,
                         cudaFuncAttributeMaxDynamicSharedMemorySize, smem_bytes);
    cudaFuncSetAttribute(hgemm_kernel<1, HID, INTR>,
                         cudaFuncAttributeMaxDynamicSharedMemorySize, smem_bytes);

    prep_kernel<0, HID, INTR><<<2304 + 192, 256>>>(W1, tag_emb, Wv, bv);
    prep_kernel<1, INTR, HID><<<2304 + 192, 256>>>(W2, nullptr, Wo, bo);

    ln1_kernel<<<TOKENS, 256>>>(we, tags, mask, ln1g, ln1b);

    hgemm_kernel<0, INTR, HID>
        <<<dim3(INTR / 128, TOKENS / 128), 128, smem_bytes>>>(b1);

    hgemm_kernel<1, HID, INTR>
        <<<dim3(HID / 128, TOKENS / 128), 128, smem_bytes>>>(b2);

    ln2_kernel<<<TOKENS, 256>>>(ln2g, ln2b, out);
}

// round 12
// speedup vs baseline: 1.7015x; 1.0396x over previous
#include <cuda_runtime.h>
#include <cuda_fp16.h>
#include <cstdint>

#define TOKENS 32768
#define HID 768
#define INTR 3072
#define NTAGS 64

// ---------------------------------------------------------------------------
// Scratch (static device memory — allocation-free per harness rules)
// ---------------------------------------------------------------------------
__device__ __align__(256) __half g_x[(size_t)TOKENS * HID];    // LN1 out (fp16)
__device__ __align__(256) __half g_h[(size_t)TOKENS * INTR];   // relu(x@W1+b1) fp16
__device__ __align__(256) float  g_ffx[(size_t)TOKENS * HID];  // ff + x (fp32)
__device__ __align__(256) __half g_w1t[(size_t)INTR * HID];    // W1^T [n][k] fp16
__device__ __align__(256) __half g_w2t[(size_t)HID * INTR];    // W2^T [n][k] fp16
__device__ __align__(256) float  g_tmp[NTAGS * HID];           // tag_emb@Wv+bv
__device__ __align__(256) float  g_ptag[NTAGS * HID];          // per-tag vector

// ---------------------------------------------------------------------------
// Helpers
// ---------------------------------------------------------------------------
__device__ __forceinline__ void cp_async16(uint32_t saddr, const void* gaddr) {
    asm volatile("cp.async.cg.shared.global [%0], [%1], 16;" :: "r"(saddr), "l"(gaddr));
}
__device__ __forceinline__ void cp_commit() { asm volatile("cp.async.commit_group;"); }
template<int N> __device__ __forceinline__ void cp_wait() {
    asm volatile("cp.async.wait_group %0;" :: "n"(N));
}

__device__ __forceinline__ void mma_f16(float c[4], const uint32_t a[4],
                                        uint32_t b0, uint32_t b1) {
    asm volatile(
        "mma.sync.aligned.m16n8k16.row.col.f32.f16.f16.f32 "
        "{%0,%1,%2,%3}, {%4,%5,%6,%7}, {%8,%9}, {%0,%1,%2,%3};"
        : "+f"(c[0]), "+f"(c[1]), "+f"(c[2]), "+f"(c[3])
        : "r"(a[0]), "r"(a[1]), "r"(a[2]), "r"(a[3]), "r"(b0), "r"(b1));
}

__device__ __forceinline__ void ldsm_x4(uint32_t r[4], uint32_t addr) {
    asm volatile("ldmatrix.sync.aligned.m8n8.x4.shared.b16 {%0,%1,%2,%3}, [%4];"
        : "=r"(r[0]), "=r"(r[1]), "=r"(r[2]), "=r"(r[3]) : "r"(addr));
}

// ---------------------------------------------------------------------------
// Fused prep kernel: weight transpose+round -> half [n][k], plus tag GEMV tail
// ---------------------------------------------------------------------------
template<int WHICH, int K, int N>
__global__ void __launch_bounds__(256)
prep_kernel(const float* __restrict__ W,
            const float* __restrict__ E,
            const float* __restrict__ Wt,
            const float* __restrict__ bt) {
    __shared__ float sbuf[32 * 33];
    constexpr int TB = (N / 32) * (K / 32);
    const int tid = threadIdx.x;
    const int bid = blockIdx.x;

    if (bid < TB) {
        int nb = bid % (N / 32), kb = bid / (N / 32);
        int tx = tid & 31, ty = tid >> 5;
        float (*tile)[33] = (float(*)[33])sbuf;
#pragma unroll
        for (int i = ty; i < 32; i += 8)
            tile[i][tx] = W[(long)(kb * 32 + i) * N + nb * 32 + tx];
        __syncthreads();
        __half* out = WHICH ? g_w2t : g_w1t;
#pragma unroll
        for (int i = ty; i < 32; i += 8)
            out[(long)(nb * 32 + i) * K + kb * 32 + tx] = __float2half_rn(tile[tx][i]);
    } else {
        int b2 = bid - TB;
        int t = b2 / 3, chunk = b2 - t * 3;
        int n = chunk * 256 + tid;
        const float* Es = WHICH ? g_tmp : E;
        float* O = WHICH ? g_ptag : g_tmp;
        for (int c = tid; c < HID; c += 256) sbuf[c] = Es[t * HID + c];
        __syncthreads();
        float a0 = bt[n], a1 = 0.f, a2 = 0.f, a3 = 0.f;
        for (int k = 0; k < HID; k += 8) {
            float w0 = Wt[(long)(k + 0) * HID + n];
            float w1 = Wt[(long)(k + 1) * HID + n];
            float w2 = Wt[(long)(k + 2) * HID + n];
            float w3 = Wt[(long)(k + 3) * HID + n];
            float w4 = Wt[(long)(k + 4) * HID + n];
            float w5 = Wt[(long)(k + 5) * HID + n];
            float w6 = Wt[(long)(k + 6) * HID + n];
            float w7 = Wt[(long)(k + 7) * HID + n];
            a0 = fmaf(sbuf[k + 0], w0, a0);
            a1 = fmaf(sbuf[k + 1], w1, a1);
            a2 = fmaf(sbuf[k + 2], w2, a2);
            a3 = fmaf(sbuf[k + 3], w3, a3);
            a0 = fmaf(sbuf[k + 4], w4, a0);
            a1 = fmaf(sbuf[k + 5], w5, a1);
            a2 = fmaf(sbuf[k + 6], w6, a2);
            a3 = fmaf(sbuf[k + 7], w7, a3);
        }
        O[t * HID + n] = (a0 + a1) + (a2 + a3);
    }
}

// ---------------------------------------------------------------------------
// Block reduce for (sum, sumsq) over 256 threads
// ---------------------------------------------------------------------------
__device__ __forceinline__ void block_reduce2(float& s, float& s2, float* red) {
#pragma unroll
    for (int o = 16; o > 0; o >>= 1) {
        s  += __shfl_xor_sync(0xffffffffu, s,  o);
        s2 += __shfl_xor_sync(0xffffffffu, s2, o);
    }
    int warp = threadIdx.x >> 5, lane = threadIdx.x & 31;
    if (lane == 0) { red[warp] = s; red[8 + warp] = s2; }
    __syncthreads();
    if (warp == 0) {
        float a  = (lane < 8) ? red[lane] : 0.f;
        float a2 = (lane < 8) ? red[8 + lane] : 0.f;
#pragma unroll
        for (int o = 4; o > 0; o >>= 1) {
            a  += __shfl_xor_sync(0xffffffffu, a,  o);
            a2 += __shfl_xor_sync(0xffffffffu, a2, o);
        }
        if (lane == 0) { red[16] = a; red[17] = a2; }
    }
    __syncthreads();
    s = red[16]; s2 = red[17];
}

// ---------------------------------------------------------------------------
// LN1: g_x = fp16_rn( LN( we + per_tag[tag]*mask ) * g + b )
// ---------------------------------------------------------------------------
__global__ void __launch_bounds__(256)
ln1_kernel(const float* __restrict__ we, const int* __restrict__ tags,
           const int* __restrict__ mask,
           const float* __restrict__ g, const float* __restrict__ b) {
    __shared__ float red[18];
    long row = blockIdx.x;
    const float* wr = we + row * HID;
    const float* pr = g_ptag + (long)tags[row] * HID;
    float mk = (float)mask[row];
    int t = threadIdx.x;
    float v[3]; float s = 0.f, s2 = 0.f;
#pragma unroll
    for (int j = 0; j < 3; j++) {
        int c = t + j * 256;
        float val = wr[c] + pr[c] * mk;
        v[j] = val; s += val; s2 += val * val;
    }
    block_reduce2(s, s2, red);
    float mu = s * (1.f / 768.f);
    float var = s2 * (1.f / 768.f) - mu * mu;
    float rs = rsqrtf(var + 1e-12f);
#pragma unroll
    for (int j = 0; j < 3; j++) {
        int c = t + j * 256;
        g_x[row * HID + c] = __float2half_rn((v[j] - mu) * rs * g[c] + b[c]);
    }
}

// ---------------------------------------------------------------------------
// LN2: out = LN(g_ffx) * g + b
// ---------------------------------------------------------------------------
__global__ void __launch_bounds__(256)
ln2_kernel(const float* __restrict__ g, const float* __restrict__ b,
           float* __restrict__ out) {
    __shared__ float red[18];
    long row = blockIdx.x;
    const float* in = g_ffx + row * HID;
    int t = threadIdx.x;
    float v[3]; float s = 0.f, s2 = 0.f;
#pragma unroll
    for (int j = 0; j < 3; j++) {
        int c = t + j * 256;
        float val = in[c];
        v[j] = val; s += val; s2 += val * val;
    }
    block_reduce2(s, s2, red);
    float mu = s * (1.f / 768.f);
    float var = s2 * (1.f / 768.f) - mu * mu;
    float rs = rsqrtf(var + 1e-12f);
#pragma unroll
    for (int j = 0; j < 3; j++) {
        int c = t + j * 256;
        out[row * HID + c] = (v[j] - mu) * rs * g[c] + b[c];
    }
}

// ---------------------------------------------------------------------------
// fp16 mma.sync GEMM: 128x128 CTA tile, 128 threads = 4 warps of 64x64 (2x2).
//   MODE 0: A=g_x,  Bt=g_w1t, C=g_h   (half), epi = fp16_rn(relu(acc+bias))
//   MODE 1: A=g_h,  Bt=g_w2t, C=g_ffx (fp32), epi = acc+bias+float(g_x)
// BK=64 halves (128B rows), XOR swizzle, ldmatrix.x4, NS=3 ring
// (wait_group<1>, ONE sync per tile, load t+2).
// __launch_bounds__(128, 2): reg cap 256 -> explicit fragment double-buffer
// across k16 steps (the reg slack R8/R10/R11 never had). 2 CTAs/SM = 8 warps
// = 2/SMSP, each with always-ready MMA bursts -> tensor-pipe-bound.
// ---------------------------------------------------------------------------
template<int MODE, int N, int K>
__global__ void __launch_bounds__(128, 2)
hgemm_kernel(const float* __restrict__ bias) {
    constexpr int BM = 128, BK = 64;             // BK in halves; 128 B per row
    constexpr int ABYTES = BM * BK * 2;          // 16 KB
    constexpr int STG = 2 * ABYTES;              // A + B = 32 KB per stage
    constexpr int NS = 3;                        // 96 KB smem per CTA

    extern __shared__ __align__(16) char smem_raw[];

    const __half* A  = MODE ? g_h   : g_x;
    const __half* Bt = MODE ? g_w2t : g_w1t;

    const int tid = threadIdx.x;
    const int lane = tid & 31;
    const int warp = tid >> 5;                   // 0..3
    const int wr = (warp & 1) * 64;              // warp row (0/64)
    const int wc = (warp >> 1) * 64;             // warp col (0/64)
    const long blockRow = (long)blockIdx.y * BM;
    const int  blockCol = blockIdx.x * 128;

    float acc[4][8][4];
#pragma unroll
    for (int mi = 0; mi < 4; mi++)
#pragma unroll
        for (int ni = 0; ni < 8; ni++)
#pragma unroll
            for (int r = 0; r < 4; r++) acc[mi][ni][r] = 0.f;

    const uint32_t sbase = (uint32_t)__cvta_generic_to_shared(smem_raw);

    // ldmatrix lane mappings (validated R8/R10/R11) — hoisted once.
    const int  rA_lane = wr + (lane & 15);
    const uint32_t eA = (uint32_t)(lane >> 4);
    const int  rB_lane = wc + ((lane & 16) >> 1) + (lane & 7);
    const uint32_t eB = (uint32_t)((lane >> 3) & 1);
    uint32_t aOff[4], aKey[4], bOff[4], bKey[4];
#pragma unroll
    for (int mi = 0; mi < 4; mi++) {
        int r = rA_lane + mi * 16;
        aOff[mi] = (uint32_t)(r * 128);
        aKey[mi] = (uint32_t)(r & 7);
    }
#pragma unroll
    for (int p = 0; p < 4; p++) {
        int r = rB_lane + p * 16;
        bOff[p] = (uint32_t)(r * 128);
        bKey[p] = (uint32_t)(r & 7);
    }

    auto load_tile = [&](int kt, int st) {
        uint32_t base = sbase + (uint32_t)st * STG;
        // A: 128 rows x 8 chunks = 1024 -> 8 per thread (128 threads)
#pragma unroll
        for (int i = 0; i < 8; i++) {
            int idx = tid + i * 128;
            int r = idx >> 3, c = idx & 7;
            const __half* gp = A + (blockRow + r) * (long)K + kt * BK + c * 8;
            cp_async16(base + (uint32_t)(r * 128 + ((c ^ (r & 7)) << 4)), gp);
        }
        // B: 128 n-rows x 8 chunks = 1024 -> 8 per thread
#pragma unroll
        for (int i = 0; i < 8; i++) {
            int idx = tid + i * 128;
            int r = idx >> 3, c = idx & 7;
            const __half* gp = Bt + (long)(blockCol + r) * K + kt * BK + c * 8;
            cp_async16(base + ABYTES + (uint32_t)(r * 128 + ((c ^ (r & 7)) << 4)), gp);
        }
        cp_commit();
    };

    load_tile(0, 0);
    load_tile(1, 1);

    const int kTiles = K / BK;                   // 12 or 48
    for (int t = 0; t < kTiles; t++) {
        cp_wait<1>();                            // tile t resident (t+1 may pend)
        __syncthreads();                         // all warps done with stage (t-1)%3
        if (t + 2 < kTiles) load_tile(t + 2, (t + 2) % NS);
        else cp_commit();                        // keep group arithmetic exact

        const uint32_t sa = sbase + (uint32_t)(t % NS) * STG;
        const uint32_t sb = sa + ABYTES;

        // Fragment double-buffer across the 4 k16 steps.
        uint32_t af[2][4][4], bf[2][4][4];
        auto ldfrags = [&](int s, int buf) {
            const uint32_t cA = (uint32_t)(s * 2) + eA;
            const uint32_t cB = (uint32_t)(s * 2) + eB;
#pragma unroll
            for (int mi = 0; mi < 4; mi++)
                ldsm_x4(af[buf][mi], sa + aOff[mi] + ((cA ^ aKey[mi]) << 4));
#pragma unroll
            for (int p = 0; p < 4; p++)
                ldsm_x4(bf[buf][p], sb + bOff[p] + ((cB ^ bKey[p]) << 4));
        };

        ldfrags(0, 0);
#pragma unroll
        for (int s = 0; s < 4; s++) {
            if (s < 3) ldfrags(s + 1, (s + 1) & 1);   // prefetch next step
            const int b = s & 1;
#pragma unroll
            for (int mi = 0; mi < 4; mi++) {
#pragma unroll
                for (int p = 0; p < 4; p++) {
                    mma_f16(acc[mi][2 * p + 0], af[b][mi], bf[b][p][0], bf[b][p][1]);
                    mma_f16(acc[mi][2 * p + 1], af[b][mi], bf[b][p][2], bf[b][p][3]);
                }
            }
        }
    }

    // ---- Epilogue ----
#pragma unroll
    for (int mi = 0; mi < 4; mi++) {
#pragma unroll
        for (int ri = 0; ri < 2; ri++) {
            long row = blockRow + wr + mi * 16 + (lane >> 2) + ri * 8;
#pragma unroll
            for (int ni = 0; ni < 8; ni++) {
                int col = blockCol + wc + ni * 8 + (lane & 3) * 2;
                float v0 = acc[mi][ni][ri * 2 + 0] + bias[col];
                float v1 = acc[mi][ni][ri * 2 + 1] + bias[col + 1];
                if (MODE == 0) {
                    __half2 h2;
                    h2.x = __float2half_rn(fmaxf(v0, 0.f));
                    h2.y = __float2half_rn(fmaxf(v1, 0.f));
                    *(__half2*)(g_h + row * (long)N + col) = h2;
                } else {
                    __half2 x2 = *(const __half2*)(g_x + row * HID + col);
                    float2 o;
                    o.x = v0 + __half2float(x2.x);
                    o.y = v1 + __half2float(x2.y);
                    *(float2*)(g_ffx + row * (long)N + col) = o;
                }
            }
        }
    }
}

// ---------------------------------------------------------------------------
// Launch  (order keeps gemm1 at the ncu-captured slot #4)
// ---------------------------------------------------------------------------
extern "C" void kernel_launch(void* const* d_in, const int* in_sizes, int n_in,
                              void* d_out, int out_size) {
    const float* we      = (const float*)d_in[0];
    const int*   tags    = (const int*)d_in[1];
    const int*   mask    = (const int*)d_in[2];
    const float* tag_emb = (const float*)d_in[3];
    const float* Wv      = (const float*)d_in[4];
    const float* bv      = (const float*)d_in[5];
    const float* Wo      = (const float*)d_in[6];
    const float* bo      = (const float*)d_in[7];
    const float* ln1g    = (const float*)d_in[8];
    const float* ln1b    = (const float*)d_in[9];
    const float* W1      = (const float*)d_in[10];
    const float* b1      = (const float*)d_in[11];
    const float* W2      = (const float*)d_in[12];
    const float* b2      = (const float*)d_in[13];
    const float* ln2g    = (const float*)d_in[14];
    const float* ln2b    = (const float*)d_in[15];
    float* out = (float*)d_out;

    const int smem_bytes = 3 * 2 * 128 * 64 * 2;   // 98304 B (3 stages x 32 KB)
    cudaFuncSetAttribute(hgemm_kernel<0, INTR, HID>,
                         cudaFuncAttributeMaxDynamicSharedMemorySize, smem_bytes);
    cudaFuncSetAttribute(hgemm_kernel<1, HID, INTR>,
                         cudaFuncAttributeMaxDynamicSharedMemorySize, smem_bytes);

    prep_kernel<0, HID, INTR><<<2304 + 192, 256>>>(W1, tag_emb, Wv, bv);
    prep_kernel<1, INTR, HID><<<2304 + 192, 256>>>(W2, nullptr, Wo, bo);

    ln1_kernel<<<TOKENS, 256>>>(we, tags, mask, ln1g, ln1b);

    hgemm_kernel<0, INTR, HID>
        <<<dim3(INTR / 128, TOKENS / 128), 128, smem_bytes>>>(b1);

    hgemm_kernel<1, HID, INTR>
        <<<dim3(HID / 128, TOKENS / 128), 128, smem_bytes>>>(b2);

    ln2_kernel<<<TOKENS, 256>>>(ln2g, ln2b, out);
}

// round 14
// speedup vs baseline: 1.8269x; 1.0737x over previous
#include <cuda_runtime.h>
#include <cuda_fp16.h>
#include <cstdint>

#define TOKENS 32768
#define HID 768
#define INTR 3072
#define NTAGS 64

// ---------------------------------------------------------------------------
// Scratch (static device memory — allocation-free per harness rules)
// ---------------------------------------------------------------------------
__device__ __align__(256) __half g_x[(size_t)TOKENS * HID];    // LN1 out (fp16)
__device__ __align__(256) __half g_h[(size_t)TOKENS * INTR];   // relu(x@W1+b1) fp16
__device__ __align__(256) __half g_ffx[(size_t)TOKENS * HID];  // ff + x (fp16)
__device__ __align__(256) __half g_w1t[(size_t)INTR * HID];    // W1^T [n][k] fp16
__device__ __align__(256) __half g_w2t[(size_t)HID * INTR];    // W2^T [n][k] fp16
__device__ __align__(256) float  g_tmp[NTAGS * HID];           // tag_emb@Wv+bv
__device__ __align__(256) float  g_ptag[NTAGS * HID];          // per-tag vector

// ---------------------------------------------------------------------------
// Helpers
// ---------------------------------------------------------------------------
__device__ __forceinline__ void cp_async16(uint32_t saddr, const void* gaddr) {
    asm volatile("cp.async.cg.shared.global [%0], [%1], 16;" :: "r"(saddr), "l"(gaddr));
}
__device__ __forceinline__ void cp_commit() { asm volatile("cp.async.commit_group;"); }
template<int N> __device__ __forceinline__ void cp_wait() {
    asm volatile("cp.async.wait_group %0;" :: "n"(N));
}

__device__ __forceinline__ void mma_f16(float c[4], const uint32_t a[4],
                                        uint32_t b0, uint32_t b1) {
    asm volatile(
        "mma.sync.aligned.m16n8k16.row.col.f32.f16.f16.f32 "
        "{%0,%1,%2,%3}, {%4,%5,%6,%7}, {%8,%9}, {%0,%1,%2,%3};"
        : "+f"(c[0]), "+f"(c[1]), "+f"(c[2]), "+f"(c[3])
        : "r"(a[0]), "r"(a[1]), "r"(a[2]), "r"(a[3]), "r"(b0), "r"(b1));
}

__device__ __forceinline__ void ldsm_x4(uint32_t r[4], uint32_t addr) {
    asm volatile("ldmatrix.sync.aligned.m8n8.x4.shared.b16 {%0,%1,%2,%3}, [%4];"
        : "=r"(r[0]), "=r"(r[1]), "=r"(r[2]), "=r"(r[3]) : "r"(addr));
}

// ---------------------------------------------------------------------------
// Fused prep kernel: weight transpose+round -> half [n][k], plus tag GEMV tail
// ---------------------------------------------------------------------------
template<int WHICH, int K, int N>
__global__ void __launch_bounds__(256)
prep_kernel(const float* __restrict__ W,
            const float* __restrict__ E,
            const float* __restrict__ Wt,
            const float* __restrict__ bt) {
    __shared__ float sbuf[32 * 33];
    constexpr int TB = (N / 32) * (K / 32);
    const int tid = threadIdx.x;
    const int bid = blockIdx.x;

    if (bid < TB) {
        int nb = bid % (N / 32), kb = bid / (N / 32);
        int tx = tid & 31, ty = tid >> 5;
        float (*tile)[33] = (float(*)[33])sbuf;
#pragma unroll
        for (int i = ty; i < 32; i += 8)
            tile[i][tx] = W[(long)(kb * 32 + i) * N + nb * 32 + tx];
        __syncthreads();
        __half* out = WHICH ? g_w2t : g_w1t;
#pragma unroll
        for (int i = ty; i < 32; i += 8)
            out[(long)(nb * 32 + i) * K + kb * 32 + tx] = __float2half_rn(tile[tx][i]);
    } else {
        int b2 = bid - TB;
        int t = b2 / 3, chunk = b2 - t * 3;
        int n = chunk * 256 + tid;
        const float* Es = WHICH ? g_tmp : E;
        float* O = WHICH ? g_ptag : g_tmp;
        for (int c = tid; c < HID; c += 256) sbuf[c] = Es[t * HID + c];
        __syncthreads();
        float a0 = bt[n], a1 = 0.f, a2 = 0.f, a3 = 0.f;
        for (int k = 0; k < HID; k += 8) {
            float w0 = Wt[(long)(k + 0) * HID + n];
            float w1 = Wt[(long)(k + 1) * HID + n];
            float w2 = Wt[(long)(k + 2) * HID + n];
            float w3 = Wt[(long)(k + 3) * HID + n];
            float w4 = Wt[(long)(k + 4) * HID + n];
            float w5 = Wt[(long)(k + 5) * HID + n];
            float w6 = Wt[(long)(k + 6) * HID + n];
            float w7 = Wt[(long)(k + 7) * HID + n];
            a0 = fmaf(sbuf[k + 0], w0, a0);
            a1 = fmaf(sbuf[k + 1], w1, a1);
            a2 = fmaf(sbuf[k + 2], w2, a2);
            a3 = fmaf(sbuf[k + 3], w3, a3);
            a0 = fmaf(sbuf[k + 4], w4, a0);
            a1 = fmaf(sbuf[k + 5], w5, a1);
            a2 = fmaf(sbuf[k + 6], w6, a2);
            a3 = fmaf(sbuf[k + 7], w7, a3);
        }
        O[t * HID + n] = (a0 + a1) + (a2 + a3);
    }
}

// ---------------------------------------------------------------------------
// Block reduce for (sum, sumsq) over 192 threads (6 warps)
// ---------------------------------------------------------------------------
__device__ __forceinline__ void block_reduce2_192(float& s, float& s2, float* red) {
#pragma unroll
    for (int o = 16; o > 0; o >>= 1) {
        s  += __shfl_xor_sync(0xffffffffu, s,  o);
        s2 += __shfl_xor_sync(0xffffffffu, s2, o);
    }
    int warp = threadIdx.x >> 5, lane = threadIdx.x & 31;
    if (lane == 0) { red[warp] = s; red[6 + warp] = s2; }
    __syncthreads();
    if (warp == 0) {
        float a  = (lane < 6) ? red[lane] : 0.f;
        float a2 = (lane < 6) ? red[6 + lane] : 0.f;
#pragma unroll
        for (int o = 4; o > 0; o >>= 1) {
            a  += __shfl_xor_sync(0xffffffffu, a,  o);
            a2 += __shfl_xor_sync(0xffffffffu, a2, o);
        }
        if (lane == 0) { red[12] = a; red[13] = a2; }
    }
    __syncthreads();
    s = red[12]; s2 = red[13];
}

// ---------------------------------------------------------------------------
// LN1 (vectorized): g_x = fp16_rn( LN( we + ptag[tag]*mask ) * g + b )
// ---------------------------------------------------------------------------
__global__ void __launch_bounds__(192)
ln1_kernel(const float* __restrict__ we, const int* __restrict__ tags,
           const int* __restrict__ mask,
           const float* __restrict__ g, const float* __restrict__ b) {
    __shared__ float red[14];
    long row = blockIdx.x;
    int t = threadIdx.x;
    float mk = (float)mask[row];
    float4 w4 = *(const float4*)(we + row * HID + t * 4);
    float4 p4 = *(const float4*)(g_ptag + (long)tags[row] * HID + t * 4);
    float v[4] = { w4.x + p4.x * mk, w4.y + p4.y * mk,
                   w4.z + p4.z * mk, w4.w + p4.w * mk };
    float s = (v[0] + v[1]) + (v[2] + v[3]);
    float s2 = (v[0] * v[0] + v[1] * v[1]) + (v[2] * v[2] + v[3] * v[3]);
    block_reduce2_192(s, s2, red);
    float mu = s * (1.f / 768.f);
    float var = s2 * (1.f / 768.f) - mu * mu;
    float rs = rsqrtf(var + 1e-12f);
    float4 g4 = *(const float4*)(g + t * 4);
    float4 b4 = *(const float4*)(b + t * 4);
    __half2 o0, o1;
    o0.x = __float2half_rn((v[0] - mu) * rs * g4.x + b4.x);
    o0.y = __float2half_rn((v[1] - mu) * rs * g4.y + b4.y);
    o1.x = __float2half_rn((v[2] - mu) * rs * g4.z + b4.z);
    o1.y = __float2half_rn((v[3] - mu) * rs * g4.w + b4.w);
    __half2* dst = (__half2*)(g_x + row * HID + t * 4);
    dst[0] = o0; dst[1] = o1;
}

// ---------------------------------------------------------------------------
// LN2 (vectorized): out = LN(g_ffx fp16) * g + b   (fp32 output)
// ---------------------------------------------------------------------------
__global__ void __launch_bounds__(192)
ln2_kernel(const float* __restrict__ g, const float* __restrict__ b,
           float* __restrict__ out) {
    __shared__ float red[14];
    long row = blockIdx.x;
    int t = threadIdx.x;
    const __half2* src = (const __half2*)(g_ffx + row * HID + t * 4);
    float2 a0 = __half22float2(src[0]);
    float2 a1 = __half22float2(src[1]);
    float v[4] = { a0.x, a0.y, a1.x, a1.y };
    float s = (v[0] + v[1]) + (v[2] + v[3]);
    float s2 = (v[0] * v[0] + v[1] * v[1]) + (v[2] * v[2] + v[3] * v[3]);
    block_reduce2_192(s, s2, red);
    float mu = s * (1.f / 768.f);
    float var = s2 * (1.f / 768.f) - mu * mu;
    float rs = rsqrtf(var + 1e-12f);
    float4 g4 = *(const float4*)(g + t * 4);
    float4 b4 = *(const float4*)(b + t * 4);
    float4 o;
    o.x = (v[0] - mu) * rs * g4.x + b4.x;
    o.y = (v[1] - mu) * rs * g4.y + b4.y;
    o.z = (v[2] - mu) * rs * g4.z + b4.z;
    o.w = (v[3] - mu) * rs * g4.w + b4.w;
    *(float4*)(out + row * HID + t * 4) = o;
}

// ---------------------------------------------------------------------------
// fp16 mma.sync GEMM: 128x128 CTA tile, 128 threads = 4 warps of 64x64 (2x2).
//   MODE 0: A=g_x,  Bt=g_w1t, C=g_h   (half), epi = fp16_rn(relu(acc+bias))
//   MODE 1: A=g_h,  Bt=g_w2t, C=g_ffx (half), epi = acc+bias+float(g_x)
// BK=64 halves (128B rows), XOR swizzle, ldmatrix.x4, NS=3 ring.
// Cross-tile fragment prefetch with RACE-FIXED ordering: the one barrier per
// tile sits between cp_wait<1> and the tile-(t+1) step-0 fragment loads, so
// every cp.async (per-thread completion!) is CTA-visible before any ldsm
// reads it. load_tile(t+2) at top of iter t writes stage (t-1)%3, whose
// readers all passed the previous end-of-iter barrier.
// ---------------------------------------------------------------------------
template<int MODE, int N, int K>
__global__ void __launch_bounds__(128, 2)
hgemm_kernel(const float* __restrict__ bias) {
    constexpr int BM = 128, BK = 64;             // BK in halves; 128 B per row
    constexpr int ABYTES = BM * BK * 2;          // 16 KB
    constexpr int STG = 2 * ABYTES;              // A + B = 32 KB per stage
    constexpr int NS = 3;                        // 96 KB smem per CTA

    extern __shared__ __align__(16) char smem_raw[];

    const __half* A  = MODE ? g_h   : g_x;
    const __half* Bt = MODE ? g_w2t : g_w1t;

    const int tid = threadIdx.x;
    const int lane = tid & 31;
    const int warp = tid >> 5;                   // 0..3
    const int wr = (warp & 1) * 64;              // warp row (0/64)
    const int wc = (warp >> 1) * 64;             // warp col (0/64)
    const long blockRow = (long)blockIdx.y * BM;
    const int  blockCol = blockIdx.x * 128;

    float acc[4][8][4];
#pragma unroll
    for (int mi = 0; mi < 4; mi++)
#pragma unroll
        for (int ni = 0; ni < 8; ni++)
#pragma unroll
            for (int r = 0; r < 4; r++) acc[mi][ni][r] = 0.f;

    const uint32_t sbase = (uint32_t)__cvta_generic_to_shared(smem_raw);

    // ldmatrix lane mappings (validated R8/R10/R11/R12) — hoisted once.
    const int  rA_lane = wr + (lane & 15);
    const uint32_t eA = (uint32_t)(lane >> 4);
    const int  rB_lane = wc + ((lane & 16) >> 1) + (lane & 7);
    const uint32_t eB = (uint32_t)((lane >> 3) & 1);
    uint32_t aOff[4], aKey[4], bOff[4], bKey[4];
#pragma unroll
    for (int mi = 0; mi < 4; mi++) {
        int r = rA_lane + mi * 16;
        aOff[mi] = (uint32_t)(r * 128);
        aKey[mi] = (uint32_t)(r & 7);
    }
#pragma unroll
    for (int p = 0; p < 4; p++) {
        int r = rB_lane + p * 16;
        bOff[p] = (uint32_t)(r * 128);
        bKey[p] = (uint32_t)(r & 7);
    }

    auto load_tile = [&](int kt, int st) {
        uint32_t base = sbase + (uint32_t)st * STG;
#pragma unroll
        for (int i = 0; i < 8; i++) {            // A: 1024 chunks / 128 thr
            int idx = tid + i * 128;
            int r = idx >> 3, c = idx & 7;
            const __half* gp = A + (blockRow + r) * (long)K + kt * BK + c * 8;
            cp_async16(base + (uint32_t)(r * 128 + ((c ^ (r & 7)) << 4)), gp);
        }
#pragma unroll
        for (int i = 0; i < 8; i++) {            // B: 1024 chunks / 128 thr
            int idx = tid + i * 128;
            int r = idx >> 3, c = idx & 7;
            const __half* gp = Bt + (long)(blockCol + r) * K + kt * BK + c * 8;
            cp_async16(base + ABYTES + (uint32_t)(r * 128 + ((c ^ (r & 7)) << 4)), gp);
        }
        cp_commit();
    };

    // Fragment double-buffer (per k16 step; buf0 always holds step 0).
    uint32_t af[2][4][4], bf[2][4][4];
    auto ldfrags = [&](uint32_t sa, int s, int buf) {
        const uint32_t sb = sa + ABYTES;
        const uint32_t cA = (uint32_t)(s * 2) + eA;
        const uint32_t cB = (uint32_t)(s * 2) + eB;
#pragma unroll
        for (int mi = 0; mi < 4; mi++)
            ldsm_x4(af[buf][mi], sa + aOff[mi] + ((cA ^ aKey[mi]) << 4));
#pragma unroll
        for (int p = 0; p < 4; p++)
            ldsm_x4(bf[buf][p], sb + bOff[p] + ((cB ^ bKey[p]) << 4));
    };

    load_tile(0, 0);
    load_tile(1, 1);
    cp_wait<1>();                                // this thread's tile-0 copies done
    __syncthreads();                             // ...made CTA-visible
    ldfrags(sbase, 0, 0);                        // preload tile 0 step 0 (safe)

    const int kTiles = K / BK;                   // 12 or 48
    for (int t = 0; t < kTiles; t++) {
        // Stage (t+2)%3 == (t-1)%3: all its readers passed the previous
        // end-of-iteration barrier, so overwriting is safe.
        if (t + 2 < kTiles) load_tile(t + 2, (t + 2) % NS);
        else cp_commit();                        // keep group arithmetic exact

        const uint32_t sa = sbase + (uint32_t)(t % NS) * STG;
#pragma unroll
        for (int s = 0; s < 4; s++) {
            if (s < 3) ldfrags(sa, s + 1, (s + 1) & 1);   // next-step prefetch
            const int b = s & 1;
#pragma unroll
            for (int mi = 0; mi < 4; mi++) {
#pragma unroll
                for (int p = 0; p < 4; p++) {
                    mma_f16(acc[mi][2 * p + 0], af[b][mi], bf[b][p][0], bf[b][p][1]);
                    mma_f16(acc[mi][2 * p + 1], af[b][mi], bf[b][p][2], bf[b][p][3]);
                }
            }
        }
        // Race-fixed cross-tile prefetch: wait + BARRIER, then read.
        if (t + 1 < kTiles) {
            cp_wait<1>();                        // tile t+1: this thread done
            __syncthreads();                     // all threads done -> visible
            ldfrags(sbase + (uint32_t)((t + 1) % NS) * STG, 0, 0);
        }
    }

    // ---- Epilogue ----
#pragma unroll
    for (int mi = 0; mi < 4; mi++) {
#pragma unroll
        for (int ri = 0; ri < 2; ri++) {
            long row = blockRow + wr + mi * 16 + (lane >> 2) + ri * 8;
#pragma unroll
            for (int ni = 0; ni < 8; ni++) {
                int col = blockCol + wc + ni * 8 + (lane & 3) * 2;
                float v0 = acc[mi][ni][ri * 2 + 0] + bias[col];
                float v1 = acc[mi][ni][ri * 2 + 1] + bias[col + 1];
                __half2 h2;
                if (MODE == 0) {
                    h2.x = __float2half_rn(fmaxf(v0, 0.f));
                    h2.y = __float2half_rn(fmaxf(v1, 0.f));
                    *(__half2*)(g_h + row * (long)N + col) = h2;
                } else {
                    __half2 x2 = *(const __half2*)(g_x + row * HID + col);
                    h2.x = __float2half_rn(v0 + __half2float(x2.x));
                    h2.y = __float2half_rn(v1 + __half2float(x2.y));
                    *(__half2*)(g_ffx + row * (long)N + col) = h2;
                }
            }
        }
    }
}

// ---------------------------------------------------------------------------
// Launch  (order keeps gemm1 at the ncu-captured slot #4)
// ---------------------------------------------------------------------------
extern "C" void kernel_launch(void* const* d_in, const int* in_sizes, int n_in,
                              void* d_out, int out_size) {
    const float* we      = (const float*)d_in[0];
    const int*   tags    = (const int*)d_in[1];
    const int*   mask    = (const int*)d_in[2];
    const float* tag_emb = (const float*)d_in[3];
    const float* Wv      = (const float*)d_in[4];
    const float* bv      = (const float*)d_in[5];
    const float* Wo      = (const float*)d_in[6];
    const float* bo      = (const float*)d_in[7];
    const float* ln1g    = (const float*)d_in[8];
    const float* ln1b    = (const float*)d_in[9];
    const float* W1      = (const float*)d_in[10];
    const float* b1      = (const float*)d_in[11];
    const float* W2      = (const float*)d_in[12];
    const float* b2      = (const float*)d_in[13];
    const float* ln2g    = (const float*)d_in[14];
    const float* ln2b    = (const float*)d_in[15];
    float* out = (float*)d_out;

    const int smem_bytes = 3 * 2 * 128 * 64 * 2;   // 98304 B (3 stages x 32 KB)
    cudaFuncSetAttribute(hgemm_kernel<0, INTR, HID>,
                         cudaFuncAttributeMaxDynamicSharedMemorySize, smem_bytes);
    cudaFuncSetAttribute(hgemm_kernel<1, HID, INTR>,
                         cudaFuncAttributeMaxDynamicSharedMemorySize, smem_bytes);

    prep_kernel<0, HID, INTR><<<2304 + 192, 256>>>(W1, tag_emb, Wv, bv);
    prep_kernel<1, INTR, HID><<<2304 + 192, 256>>>(W2, nullptr, Wo, bo);

    ln1_kernel<<<TOKENS, 192>>>(we, tags, mask, ln1g, ln1b);

    hgemm_kernel<0, INTR, HID>
        <<<dim3(INTR / 128, TOKENS / 128), 128, smem_bytes>>>(b1);

    hgemm_kernel<1, HID, INTR>
        <<<dim3(HID / 128, TOKENS / 128), 128, smem_bytes>>>(b2);

    ln2_kernel<<<TOKENS, 192>>>(ln2g, ln2b, out);
}